// round 16
// baseline (speedup 1.0000x reference)
#include <cuda_runtime.h>
#include <cuda_fp16.h>
#include <math.h>
#include <stdint.h>

// Problem constants (B=1024, R=10, L=512)
#define RR   10
#define LL   512
#define KK   1024      // 2L (halves per plane)
#define BRD  10240     // B*R
#define NLCH 8         // l-chunks of 64
#define NKO  32        // K-offset steps of 32 halves

#define FULL_TILES 1184            // exactly 4 waves at 2 CTAs/SM x 148 SMs
#define TAIL_TILES 96              // split in M -> 192 half-height CTAs

// ---------------------------------------------------------------------------
// Static device scratch (no runtime allocation allowed)
// ---------------------------------------------------------------------------
__device__ __half g_Xh[2][BRD][KK];     // fp16 hi plane of X
__device__ __half g_Xl[2][BRD][KK];     // fp16 lo plane of X
__device__ __half g_Wh[2][1024][KK];    // fp16 hi plane of 1024*W^T (n<512: Wy, else Wg)
__device__ __half g_Wl[2][1024][KK];    // fp16 lo plane
__device__ float  g_tpart[2][BRD][NLCH];
__device__ float  g_wvec[2][LL];        // [0]=wh=W1[:L]@W2, [1]=wq=W1[L:]@W2
__device__ float  g_c0;                 // b1.W2 + b2

// ---------------------------------------------------------------------------
// helpers
// ---------------------------------------------------------------------------
__device__ __forceinline__ uint32_t smem_u32(const void* p) {
    uint32_t a;
    asm("{ .reg .u64 t; cvta.to.shared.u64 t, %1; cvt.u32.u64 %0, t; }" : "=r"(a) : "l"(p));
    return a;
}
// 64-byte-row swizzle (rows are 64B here)
#define SWZ64(o) ((uint32_t)(o) ^ ((((uint32_t)(o)) >> 3) & 0x30))

__device__ __forceinline__ void cp16(uint32_t dst, const void* src) {
    asm volatile("cp.async.cg.shared.global [%0], [%1], 16;" :: "r"(dst), "l"(src) : "memory");
}
#define CP_COMMIT() asm volatile("cp.async.commit_group;" ::: "memory")

#define LDSM4(r0, r1, r2, r3, addr) \
    asm volatile("ldmatrix.sync.aligned.m8n8.x4.shared.b16 {%0,%1,%2,%3}, [%4];" \
                 : "=r"(r0), "=r"(r1), "=r"(r2), "=r"(r3) : "r"(addr))

#define MMA16816(c, a0, a1, a2, a3, b0, b1) \
    asm volatile("mma.sync.aligned.m16n8k16.row.col.f32.f16.f16.f32 " \
                 "{%0,%1,%2,%3}, {%4,%5,%6,%7}, {%8,%9}, {%0,%1,%2,%3};" \
                 : "+f"((c)[0]), "+f"((c)[1]), "+f"((c)[2]), "+f"((c)[3]) \
                 : "r"(a0), "r"(a1), "r"(a2), "r"(a3), "r"(b0), "r"(b1))

// ---------------------------------------------------------------------------
// Fused aux kernel: prep (wvec, c0) + W conversion + X conversion, one launch.
// ---------------------------------------------------------------------------
#define AUX_PREP_BLKS  128
#define AUX_WCONV_BLKS 2048
#define AUX_XCONV_BLKS 5120                 // 2560 per input (4 rows per block)
#define AUX_BLKS (AUX_PREP_BLKS + AUX_WCONV_BLKS + AUX_XCONV_BLKS)

__global__ __launch_bounds__(256)
void aux_kernel(const float* __restrict__ hist, const float* __restrict__ ques,
                const float* __restrict__ Wy_h, const float* __restrict__ Wg_h,
                const float* __restrict__ Wy_q, const float* __restrict__ Wg_q,
                const float* __restrict__ W1,   const float* __restrict__ b1,
                const float* __restrict__ W2,   const float* __restrict__ b2)
{
    __shared__ float tile[32][33];
    const int blk = blockIdx.x;
    const int t   = threadIdx.x;

    if (blk < AUX_PREP_BLKS) {
        const int warp = t >> 5;
        const int lane = t & 31;
        const int idx  = blk * 8 + warp;          // 0..1023
        float s = 0.f;
        #pragma unroll 4
        for (int m = lane; m < LL; m += 32)
            s += W1[(size_t)idx * LL + m] * W2[m];
        #pragma unroll
        for (int o = 16; o > 0; o >>= 1) s += __shfl_down_sync(0xFFFFFFFF, s, o);
        if (lane == 0) {
            if (idx < LL) g_wvec[0][idx] = s;
            else          g_wvec[1][idx - LL] = s;
        }
        if (blk == 0 && warp == 0) {
            float c = 0.f;
            #pragma unroll 4
            for (int m = lane; m < LL; m += 32) c += b1[m] * W2[m];
            #pragma unroll
            for (int o = 16; o > 0; o >>= 1) c += __shfl_down_sync(0xFFFFFFFF, c, o);
            if (lane == 0) g_c0 = c + b2[0];
        }
        return;
    }

    if (blk < AUX_PREP_BLKS + AUX_WCONV_BLKS) {
        const int wb = blk - AUX_PREP_BLKS;       // 0..2047
        const int kt = wb & 31;
        const int nt = (wb >> 5) & 31;
        const int inp = wb >> 10;
        const int tx = t & 31, ty = t >> 5;       // (32, 8)
        const float* W;
        int lbase;
        if (nt * 32 < 512) { W = inp ? Wy_q : Wy_h; lbase = nt * 32; }
        else               { W = inp ? Wg_q : Wg_h; lbase = nt * 32 - 512; }
        #pragma unroll
        for (int r = 0; r < 4; r++)
            tile[ty + r * 8][tx] = W[(size_t)(kt * 32 + ty + r * 8) * 512 + lbase + tx];
        __syncthreads();
        #pragma unroll
        for (int r = 0; r < 4; r++) {
            int nl = ty + r * 8;
            int n  = nt * 32 + nl;
            int k  = kt * 32 + tx;
            float f = tile[tx][nl] * 1024.0f;     // scale avoids fp16 denormal lo
            __half hi = __float2half_rn(f);
            __half lo = __float2half_rn(f - __half2float(hi));
            g_Wh[inp][n][k] = hi;
            g_Wl[inp][n][k] = lo;
        }
        return;
    }

    // ---- xconv: fp32 -> fp16 hi/lo planes, 4 rows per block ----
    {
        const int xb    = blk - AUX_PREP_BLKS - AUX_WCONV_BLKS;  // 0..5119
        const int input = xb / 2560;              // 2560 blocks per input
        const int row0  = (xb % 2560) * 4;
        const float* X  = input ? ques : hist;
        #pragma unroll
        for (int r = 0; r < 4; r++) {
            const int row = row0 + r;
            float4 f = *(const float4*)(X + (size_t)row * KK + t * 4);
            float fv[4] = {f.x, f.y, f.z, f.w};
            __half h[4], l[4];
            #pragma unroll
            for (int e = 0; e < 4; e++) {
                h[e] = __float2half_rn(fv[e]);
                l[e] = __float2half_rn(fv[e] - __half2float(h[e]));
            }
            *(uint2*)&g_Xh[input][row][t * 4] = *(uint2*)h;
            *(uint2*)&g_Xl[input][row][t * 4] = *(uint2*)l;
        }
    }
}

// ---------------------------------------------------------------------------
// Main GEMM (tiles 0..1183 = exactly 4 waves): R13 plane-fused body,
// flat tile decode. BM=128, BN=128(64u+64v), warps 4Mx2N, smem 3x32KB.
// ---------------------------------------------------------------------------
__global__ __launch_bounds__(256, 2)
void gemm_hmma(const float* __restrict__ by_h, const float* __restrict__ bg_h,
               const float* __restrict__ by_q, const float* __restrict__ bg_q)
{
    extern __shared__ char smem[];
    const uint32_t sbase = smem_u32(smem);
    const int tid = threadIdx.x, wid = tid >> 5, lane = tid & 31;
    const int bid = blockIdx.x;               // 0..1183
    const int input = bid / 640;
    const int rtl   = bid % 640;
    const int lc    = rtl / 80;
    const int m0    = (rtl % 80) * 128;

    const __half* Xh = &g_Xh[input][0][0];
    const __half* Xl = &g_Xl[input][0][0];
    const __half* Wh = &g_Wh[input][0][0];
    const __half* Wl = &g_Wl[input][0][0];
    const float* by_ = input ? by_q : by_h;
    const float* bg_ = input ? bg_q : bg_h;

    const uint32_t T_XH = 0, T_XL = 8192, T_WH = 16384, T_WL = 24576;

    const int ldrow = tid >> 2;        // 0..63 (+64)
    const int ldseg = tid & 3;

    const int mw = wid >> 1;
    const int nw = wid & 1;
    const int q  = lane >> 3;
    const int r  = lane & 7;
    const int tq = lane & 3;
    const int grow = lane >> 2;

    const uint32_t aq16 = (uint32_t)((q >> 1) * 16);
    const uint32_t bq16 = (uint32_t)((q & 1) * 16);
    uint32_t a_base[2], a_xor[2];
    #pragma unroll
    for (int mt = 0; mt < 2; mt++) {
        int row = mw * 32 + mt * 16 + (q & 1) * 8 + r;
        a_base[mt] = (uint32_t)(row * 64);
        a_xor[mt]  = (uint32_t)((row & 6) << 3);
    }
    uint32_t bu_base[2], bu_xor[2], bv_base[2], bv_xor[2];
    #pragma unroll
    for (int bt = 0; bt < 2; bt++) {
        int rowu = nw * 32 + bt * 16 + (q >> 1) * 8 + r;
        bu_base[bt] = (uint32_t)(rowu * 64);
        bu_xor[bt]  = (uint32_t)((rowu & 6) << 3);
        int rowv = 64 + nw * 32 + bt * 16 + (q >> 1) * 8 + r;
        bv_base[bt] = (uint32_t)(rowv * 64);
        bv_xor[bt]  = (uint32_t)((rowv & 6) << 3);
    }

    float cu[2][4][4], cv[2][4][4];
    #pragma unroll
    for (int mt = 0; mt < 2; mt++)
        #pragma unroll
        for (int ut = 0; ut < 4; ut++)
            #pragma unroll
            for (int e = 0; e < 4; e++) { cu[mt][ut][e] = 0.f; cv[mt][ut][e] = 0.f; }

    auto load_stage = [&](int ko, int st) {
        const uint32_t sb = sbase + (uint32_t)st * 32768u;
        const int kb = ko * 64 + ldseg * 16;
        #pragma unroll
        for (int i = 0; i < 2; i++) {
            const int rr  = ldrow + i * 64;
            const uint32_t dsw = SWZ64(rr * 64 + ldseg * 16);
            const size_t xoff = (size_t)(m0 + rr) * 2048 + kb;
            cp16(sb + T_XH + dsw, (const char*)Xh + xoff);
            cp16(sb + T_XL + dsw, (const char*)Xl + xoff);
            const int ng = (rr < 64) ? (lc * 64 + rr) : (448 + lc * 64 + rr);
            const size_t woff = (size_t)ng * 2048 + kb;
            cp16(sb + T_WH + dsw, (const char*)Wh + woff);
            cp16(sb + T_WL + dsw, (const char*)Wl + woff);
        }
        CP_COMMIT();
    };

    load_stage(0, 0);
    load_stage(1, 1);

    int st_cur = 0;
    int st_nxt = 2;

    #pragma unroll 1
    for (int ko = 0; ko < NKO; ko++) {
        if (ko + 1 < NKO) {
            asm volatile("cp.async.wait_group 1;" ::: "memory");
        } else {
            asm volatile("cp.async.wait_group 0;" ::: "memory");
        }
        __syncthreads();

        if (ko + 2 < NKO)
            load_stage(ko + 2, st_nxt);

        const uint32_t sb = sbase + (uint32_t)st_cur * 32768u;

        #pragma unroll
        for (int s = 0; s < 2; s++) {
            const uint32_t csA = (uint32_t)(s * 32) + aq16;
            const uint32_t csB = (uint32_t)(s * 32) + bq16;

            uint32_t a[2][4];
            #pragma unroll
            for (int mt = 0; mt < 2; mt++)
                LDSM4(a[mt][0], a[mt][1], a[mt][2], a[mt][3],
                      sb + T_XH + a_base[mt] + (csA ^ a_xor[mt]));

            // b = Wl -> p2 = Xh*Wl
            {
                uint32_t bu[2][4], bv[2][4];
                #pragma unroll
                for (int bt = 0; bt < 2; bt++) {
                    LDSM4(bu[bt][0], bu[bt][1], bu[bt][2], bu[bt][3],
                          sb + T_WL + bu_base[bt] + (csB ^ bu_xor[bt]));
                    LDSM4(bv[bt][0], bv[bt][1], bv[bt][2], bv[bt][3],
                          sb + T_WL + bv_base[bt] + (csB ^ bv_xor[bt]));
                }
                #pragma unroll
                for (int mt = 0; mt < 2; mt++)
                    #pragma unroll
                    for (int bt = 0; bt < 2; bt++) {
                        MMA16816(cu[mt][2 * bt],     a[mt][0], a[mt][1], a[mt][2], a[mt][3], bu[bt][0], bu[bt][1]);
                        MMA16816(cu[mt][2 * bt + 1], a[mt][0], a[mt][1], a[mt][2], a[mt][3], bu[bt][2], bu[bt][3]);
                        MMA16816(cv[mt][2 * bt],     a[mt][0], a[mt][1], a[mt][2], a[mt][3], bv[bt][0], bv[bt][1]);
                        MMA16816(cv[mt][2 * bt + 1], a[mt][0], a[mt][1], a[mt][2], a[mt][3], bv[bt][2], bv[bt][3]);
                    }
            }

            // b = Wh -> p0 = Xh*Wh, then a = Xl -> p1 = Xl*Wh
            {
                uint32_t bu[2][4], bv[2][4];
                #pragma unroll
                for (int bt = 0; bt < 2; bt++) {
                    LDSM4(bu[bt][0], bu[bt][1], bu[bt][2], bu[bt][3],
                          sb + T_WH + bu_base[bt] + (csB ^ bu_xor[bt]));
                    LDSM4(bv[bt][0], bv[bt][1], bv[bt][2], bv[bt][3],
                          sb + T_WH + bv_base[bt] + (csB ^ bv_xor[bt]));
                }
                #pragma unroll
                for (int mt = 0; mt < 2; mt++)
                    #pragma unroll
                    for (int bt = 0; bt < 2; bt++) {
                        MMA16816(cu[mt][2 * bt],     a[mt][0], a[mt][1], a[mt][2], a[mt][3], bu[bt][0], bu[bt][1]);
                        MMA16816(cu[mt][2 * bt + 1], a[mt][0], a[mt][1], a[mt][2], a[mt][3], bu[bt][2], bu[bt][3]);
                        MMA16816(cv[mt][2 * bt],     a[mt][0], a[mt][1], a[mt][2], a[mt][3], bv[bt][0], bv[bt][1]);
                        MMA16816(cv[mt][2 * bt + 1], a[mt][0], a[mt][1], a[mt][2], a[mt][3], bv[bt][2], bv[bt][3]);
                    }

                #pragma unroll
                for (int mt = 0; mt < 2; mt++)
                    LDSM4(a[mt][0], a[mt][1], a[mt][2], a[mt][3],
                          sb + T_XL + a_base[mt] + (csA ^ a_xor[mt]));
                #pragma unroll
                for (int mt = 0; mt < 2; mt++)
                    #pragma unroll
                    for (int bt = 0; bt < 2; bt++) {
                        MMA16816(cu[mt][2 * bt],     a[mt][0], a[mt][1], a[mt][2], a[mt][3], bu[bt][0], bu[bt][1]);
                        MMA16816(cu[mt][2 * bt + 1], a[mt][0], a[mt][1], a[mt][2], a[mt][3], bu[bt][2], bu[bt][3]);
                        MMA16816(cv[mt][2 * bt],     a[mt][0], a[mt][1], a[mt][2], a[mt][3], bv[bt][0], bv[bt][1]);
                        MMA16816(cv[mt][2 * bt + 1], a[mt][0], a[mt][1], a[mt][2], a[mt][3], bv[bt][2], bv[bt][3]);
                    }
            }
        }

        st_cur = (st_cur == 2) ? 0 : st_cur + 1;
        st_nxt = (st_nxt == 2) ? 0 : st_nxt + 1;
    }

    // ---- fused epilogue ----
    __syncthreads();
    float* red = (float*)smem;            // [128][2]
    const float INV = 1.0f / 1024.0f;
    #pragma unroll
    for (int mt = 0; mt < 2; mt++) {
        float p0 = 0.f, p1 = 0.f;
        #pragma unroll
        for (int ut = 0; ut < 4; ut++) {
            #pragma unroll
            for (int e = 0; e < 2; e++) {
                int l = lc * 64 + nw * 32 + ut * 8 + tq * 2 + e;
                float byv = __ldg(by_ + l);
                float bgv = __ldg(bg_ + l);
                float wv  = g_wvec[input][l];
                float u0 = cu[mt][ut][e] * INV + byv;
                float v0 = cv[mt][ut][e] * INV + bgv;
                p0 += tanhf(u0) * (1.f / (1.f + expf(-v0))) * wv;
                float u1 = cu[mt][ut][2 + e] * INV + byv;
                float v1 = cv[mt][ut][2 + e] * INV + bgv;
                p1 += tanhf(u1) * (1.f / (1.f + expf(-v1))) * wv;
            }
        }
        p0 += __shfl_down_sync(0xFFFFFFFF, p0, 2);
        p0 += __shfl_down_sync(0xFFFFFFFF, p0, 1);
        p1 += __shfl_down_sync(0xFFFFFFFF, p1, 2);
        p1 += __shfl_down_sync(0xFFFFFFFF, p1, 1);
        if (tq == 0) {
            int row = mw * 32 + mt * 16 + grow;
            red[row * 2 + nw]       = p0;
            red[(row + 8) * 2 + nw] = p1;
        }
    }
    __syncthreads();
    if (tid < 128)
        g_tpart[input][m0 + tid][lc] = red[tid * 2] + red[tid * 2 + 1];
}

// ---------------------------------------------------------------------------
// Tail GEMM: last 96 tiles, each split into two independent 64-row halves
// (exact M-split, no combine). 128 threads (warps 2Mx2N), BM=64, BN=128.
// smem stage 24KB x 3 = 72KB; 192 CTAs ~ one short wave after gemm_hmma.
// ---------------------------------------------------------------------------
__global__ __launch_bounds__(128, 3)
void gemm_tail(const float* __restrict__ by_h, const float* __restrict__ bg_h,
               const float* __restrict__ by_q, const float* __restrict__ bg_q)
{
    extern __shared__ char smem[];
    const uint32_t sbase = smem_u32(smem);
    const int tid = threadIdx.x, wid = tid >> 5, lane = tid & 31;

    const int sid   = blockIdx.x;             // 0..191
    const int tile  = FULL_TILES + (sid >> 1);
    const int khalf = sid & 1;                // M-half
    const int input = tile / 640;
    const int rtl   = tile % 640;
    const int lc    = rtl / 80;
    const int m0    = (rtl % 80) * 128 + khalf * 64;

    const __half* Xh = &g_Xh[input][0][0];
    const __half* Xl = &g_Xl[input][0][0];
    const __half* Wh = &g_Wh[input][0][0];
    const __half* Wl = &g_Wl[input][0][0];
    const float* by_ = input ? by_q : by_h;
    const float* bg_ = input ? bg_q : bg_h;

    // stage: Xh 4KB, Xl 4KB, Wh 8KB, Wl 8KB = 24KB
    const uint32_t T_XH = 0, T_XL = 4096, T_WH = 8192, T_WL = 16384;

    const int ldrow = tid >> 2;        // 0..31
    const int ldseg = tid & 3;

    // warp tiling: 2(M) x 2(N)
    const int mw = wid >> 1;           // 0..1
    const int nw = wid & 1;            // 0..1
    const int q  = lane >> 3;
    const int r  = lane & 7;
    const int tq = lane & 3;
    const int grow = lane >> 2;

    const uint32_t aq16 = (uint32_t)((q >> 1) * 16);
    const uint32_t bq16 = (uint32_t)((q & 1) * 16);
    uint32_t a_base[2], a_xor[2];
    #pragma unroll
    for (int mt = 0; mt < 2; mt++) {
        int row = mw * 32 + mt * 16 + (q & 1) * 8 + r;   // < 64
        a_base[mt] = (uint32_t)(row * 64);
        a_xor[mt]  = (uint32_t)((row & 6) << 3);
    }
    uint32_t bu_base[2], bu_xor[2], bv_base[2], bv_xor[2];
    #pragma unroll
    for (int bt = 0; bt < 2; bt++) {
        int rowu = nw * 32 + bt * 16 + (q >> 1) * 8 + r;
        bu_base[bt] = (uint32_t)(rowu * 64);
        bu_xor[bt]  = (uint32_t)((rowu & 6) << 3);
        int rowv = 64 + nw * 32 + bt * 16 + (q >> 1) * 8 + r;
        bv_base[bt] = (uint32_t)(rowv * 64);
        bv_xor[bt]  = (uint32_t)((rowv & 6) << 3);
    }

    float cu[2][4][4], cv[2][4][4];
    #pragma unroll
    for (int mt = 0; mt < 2; mt++)
        #pragma unroll
        for (int ut = 0; ut < 4; ut++)
            #pragma unroll
            for (int e = 0; e < 4; e++) { cu[mt][ut][e] = 0.f; cv[mt][ut][e] = 0.f; }

    auto load_stage = [&](int ko, int st) {
        const uint32_t sb = sbase + (uint32_t)st * 24576u;
        const int kb = ko * 64 + ldseg * 16;
        // X: 64 rows, 2 per plane per thread
        #pragma unroll
        for (int i = 0; i < 2; i++) {
            const int rr = ldrow + i * 32;   // 0..63
            const uint32_t dsw = SWZ64(rr * 64 + ldseg * 16);
            const size_t xoff = (size_t)(m0 + rr) * 2048 + kb;
            cp16(sb + T_XH + dsw, (const char*)Xh + xoff);
            cp16(sb + T_XL + dsw, (const char*)Xl + xoff);
        }
        // W: 128 rows, 4 per plane per thread
        #pragma unroll
        for (int i = 0; i < 4; i++) {
            const int rr = ldrow + i * 32;   // 0..127
            const uint32_t dsw = SWZ64(rr * 64 + ldseg * 16);
            const int ng = (rr < 64) ? (lc * 64 + rr) : (448 + lc * 64 + rr);
            const size_t woff = (size_t)ng * 2048 + kb;
            cp16(sb + T_WH + dsw, (const char*)Wh + woff);
            cp16(sb + T_WL + dsw, (const char*)Wl + woff);
        }
        CP_COMMIT();
    };

    load_stage(0, 0);
    load_stage(1, 1);

    int st_cur = 0;
    int st_nxt = 2;

    #pragma unroll 1
    for (int ko = 0; ko < NKO; ko++) {
        if (ko + 1 < NKO) {
            asm volatile("cp.async.wait_group 1;" ::: "memory");
        } else {
            asm volatile("cp.async.wait_group 0;" ::: "memory");
        }
        __syncthreads();

        if (ko + 2 < NKO)
            load_stage(ko + 2, st_nxt);

        const uint32_t sb = sbase + (uint32_t)st_cur * 24576u;

        #pragma unroll
        for (int s = 0; s < 2; s++) {
            const uint32_t csA = (uint32_t)(s * 32) + aq16;
            const uint32_t csB = (uint32_t)(s * 32) + bq16;

            uint32_t a[2][4];
            #pragma unroll
            for (int mt = 0; mt < 2; mt++)
                LDSM4(a[mt][0], a[mt][1], a[mt][2], a[mt][3],
                      sb + T_XH + a_base[mt] + (csA ^ a_xor[mt]));

            // b = Wl -> p2
            {
                uint32_t bu[2][4], bv[2][4];
                #pragma unroll
                for (int bt = 0; bt < 2; bt++) {
                    LDSM4(bu[bt][0], bu[bt][1], bu[bt][2], bu[bt][3],
                          sb + T_WL + bu_base[bt] + (csB ^ bu_xor[bt]));
                    LDSM4(bv[bt][0], bv[bt][1], bv[bt][2], bv[bt][3],
                          sb + T_WL + bv_base[bt] + (csB ^ bv_xor[bt]));
                }
                #pragma unroll
                for (int mt = 0; mt < 2; mt++)
                    #pragma unroll
                    for (int bt = 0; bt < 2; bt++) {
                        MMA16816(cu[mt][2 * bt],     a[mt][0], a[mt][1], a[mt][2], a[mt][3], bu[bt][0], bu[bt][1]);
                        MMA16816(cu[mt][2 * bt + 1], a[mt][0], a[mt][1], a[mt][2], a[mt][3], bu[bt][2], bu[bt][3]);
                        MMA16816(cv[mt][2 * bt],     a[mt][0], a[mt][1], a[mt][2], a[mt][3], bv[bt][0], bv[bt][1]);
                        MMA16816(cv[mt][2 * bt + 1], a[mt][0], a[mt][1], a[mt][2], a[mt][3], bv[bt][2], bv[bt][3]);
                    }
            }

            // b = Wh -> p0, then a = Xl -> p1
            {
                uint32_t bu[2][4], bv[2][4];
                #pragma unroll
                for (int bt = 0; bt < 2; bt++) {
                    LDSM4(bu[bt][0], bu[bt][1], bu[bt][2], bu[bt][3],
                          sb + T_WH + bu_base[bt] + (csB ^ bu_xor[bt]));
                    LDSM4(bv[bt][0], bv[bt][1], bv[bt][2], bv[bt][3],
                          sb + T_WH + bv_base[bt] + (csB ^ bv_xor[bt]));
                }
                #pragma unroll
                for (int mt = 0; mt < 2; mt++)
                    #pragma unroll
                    for (int bt = 0; bt < 2; bt++) {
                        MMA16816(cu[mt][2 * bt],     a[mt][0], a[mt][1], a[mt][2], a[mt][3], bu[bt][0], bu[bt][1]);
                        MMA16816(cu[mt][2 * bt + 1], a[mt][0], a[mt][1], a[mt][2], a[mt][3], bu[bt][2], bu[bt][3]);
                        MMA16816(cv[mt][2 * bt],     a[mt][0], a[mt][1], a[mt][2], a[mt][3], bv[bt][0], bv[bt][1]);
                        MMA16816(cv[mt][2 * bt + 1], a[mt][0], a[mt][1], a[mt][2], a[mt][3], bv[bt][2], bv[bt][3]);
                    }

                #pragma unroll
                for (int mt = 0; mt < 2; mt++)
                    LDSM4(a[mt][0], a[mt][1], a[mt][2], a[mt][3],
                          sb + T_XL + a_base[mt] + (csA ^ a_xor[mt]));
                #pragma unroll
                for (int mt = 0; mt < 2; mt++)
                    #pragma unroll
                    for (int bt = 0; bt < 2; bt++) {
                        MMA16816(cu[mt][2 * bt],     a[mt][0], a[mt][1], a[mt][2], a[mt][3], bu[bt][0], bu[bt][1]);
                        MMA16816(cu[mt][2 * bt + 1], a[mt][0], a[mt][1], a[mt][2], a[mt][3], bu[bt][2], bu[bt][3]);
                        MMA16816(cv[mt][2 * bt],     a[mt][0], a[mt][1], a[mt][2], a[mt][3], bv[bt][0], bv[bt][1]);
                        MMA16816(cv[mt][2 * bt + 1], a[mt][0], a[mt][1], a[mt][2], a[mt][3], bv[bt][2], bv[bt][3]);
                    }
            }
        }

        st_cur = (st_cur == 2) ? 0 : st_cur + 1;
        st_nxt = (st_nxt == 2) ? 0 : st_nxt + 1;
    }

    // ---- fused epilogue (64 rows) ----
    __syncthreads();
    float* red = (float*)smem;            // [64][2]
    const float INV = 1.0f / 1024.0f;
    #pragma unroll
    for (int mt = 0; mt < 2; mt++) {
        float p0 = 0.f, p1 = 0.f;
        #pragma unroll
        for (int ut = 0; ut < 4; ut++) {
            #pragma unroll
            for (int e = 0; e < 2; e++) {
                int l = lc * 64 + nw * 32 + ut * 8 + tq * 2 + e;
                float byv = __ldg(by_ + l);
                float bgv = __ldg(bg_ + l);
                float wv  = g_wvec[input][l];
                float u0 = cu[mt][ut][e] * INV + byv;
                float v0 = cv[mt][ut][e] * INV + bgv;
                p0 += tanhf(u0) * (1.f / (1.f + expf(-v0))) * wv;
                float u1 = cu[mt][ut][2 + e] * INV + byv;
                float v1 = cv[mt][ut][2 + e] * INV + bgv;
                p1 += tanhf(u1) * (1.f / (1.f + expf(-v1))) * wv;
            }
        }
        p0 += __shfl_down_sync(0xFFFFFFFF, p0, 2);
        p0 += __shfl_down_sync(0xFFFFFFFF, p0, 1);
        p1 += __shfl_down_sync(0xFFFFFFFF, p1, 2);
        p1 += __shfl_down_sync(0xFFFFFFFF, p1, 1);
        if (tq == 0) {
            int row = mw * 32 + mt * 16 + grow;   // < 56
            red[row * 2 + nw]       = p0;
            red[(row + 8) * 2 + nw] = p1;
        }
    }
    __syncthreads();
    if (tid < 64)
        g_tpart[input][m0 + tid][lc] = red[tid * 2] + red[tid * 2 + 1];
}

// ---------------------------------------------------------------------------
// Final: logits + Gumbel, argmax over prefix, one-hot write.
// ---------------------------------------------------------------------------
__global__ void final_kernel(const float* __restrict__ noise,
                             const float* __restrict__ Wa, const float* __restrict__ ba,
                             float* __restrict__ out)
{
    int t = blockIdx.x * blockDim.x + threadIdx.x;
    if (t >= BRD) return;
    int b = t / RR;
    int i = t % RR;

    float Wa0 = Wa[0], Wa1 = Wa[1], ba0 = ba[0], c0 = g_c0;
    float tq = 0.f;
    #pragma unroll
    for (int c = 0; c < NLCH; c++) tq += g_tpart[1][t][c];

    float best = -3.4e38f;
    int bj = 0;
    for (int j = 0; j <= i; j++) {
        float th = 0.f;
        #pragma unroll
        for (int c = 0; c < NLCH; c++) th += g_tpart[0][b * RR + j][c];
        float score = tq + th + c0;
        float logit = score * Wa0 + (float)(i - j + 1) * Wa1 + ba0;
        float ns = noise[(size_t)b * RR * RR + i * RR + j];
        float gm = -logf(1e-10f - logf(ns + 1e-10f));
        float z  = logit + gm;
        if (z > best) { best = z; bj = j; }   // strict > keeps first max
    }
    float* o = out + (size_t)b * RR * RR + (size_t)i * RR;
    #pragma unroll
    for (int j = 0; j < RR; j++) o[j] = (j == bj) ? 1.f : 0.f;
}

// ---------------------------------------------------------------------------
extern "C" void kernel_launch(void* const* d_in, const int* in_sizes, int n_in,
                              void* d_out, int out_size)
{
    const float* hist  = (const float*)d_in[0];
    const float* ques  = (const float*)d_in[1];
    const float* noise = (const float*)d_in[2];
    const float* Wy_h  = (const float*)d_in[3];
    const float* by_h  = (const float*)d_in[4];
    const float* Wg_h  = (const float*)d_in[5];
    const float* bg_h  = (const float*)d_in[6];
    const float* Wy_q  = (const float*)d_in[7];
    const float* by_q  = (const float*)d_in[8];
    const float* Wg_q  = (const float*)d_in[9];
    const float* bg_q  = (const float*)d_in[10];
    const float* W1    = (const float*)d_in[11];
    const float* b1    = (const float*)d_in[12];
    const float* W2    = (const float*)d_in[13];
    const float* b2    = (const float*)d_in[14];
    const float* Wa    = (const float*)d_in[15];
    const float* ba    = (const float*)d_in[16];
    float* out = (float*)d_out;

    cudaFuncSetAttribute(gemm_hmma, cudaFuncAttributeMaxDynamicSharedMemorySize, 98304);
    cudaFuncSetAttribute(gemm_tail, cudaFuncAttributeMaxDynamicSharedMemorySize, 73728);

    aux_kernel<<<AUX_BLKS, 256>>>(hist, ques, Wy_h, Wg_h, Wy_q, Wg_q,
                                  W1, b1, W2, b2);

    gemm_hmma<<<FULL_TILES, 256, 98304>>>(by_h, bg_h, by_q, bg_q);
    gemm_tail<<<2 * TAIL_TILES, 128, 73728>>>(by_h, bg_h, by_q, bg_q);

    final_kernel<<<(BRD + 255) / 256, 256>>>(noise, Wa, ba, out);
}

// round 17
// speedup vs baseline: 1.0444x; 1.0444x over previous
#include <cuda_runtime.h>
#include <cuda_fp16.h>
#include <math.h>
#include <stdint.h>

// Problem constants (B=1024, R=10, L=512)
#define RR   10
#define LL   512
#define KK   1024      // 2L (halves per plane)
#define BRD  10240     // B*R
#define NLCH 8         // l-chunks of 64
#define NKO  32        // K-offset steps of 32 halves

// ---------------------------------------------------------------------------
// Static device scratch (no runtime allocation allowed)
// ---------------------------------------------------------------------------
__device__ __half g_Xh[2][BRD][KK];     // fp16 hi plane of X
__device__ __half g_Xl[2][BRD][KK];     // fp16 lo plane of X
__device__ __half g_Wh[2][1024][KK];    // fp16 hi plane of 1024*W^T (n<512: Wy, else Wg)
__device__ __half g_Wl[2][1024][KK];    // fp16 lo plane
__device__ float  g_tpart[2][BRD][NLCH];
__device__ float  g_wvec[2][LL];        // [0]=wh=W1[:L]@W2, [1]=wq=W1[L:]@W2
__device__ float  g_c0;                 // b1.W2 + b2

// ---------------------------------------------------------------------------
// helpers
// ---------------------------------------------------------------------------
__device__ __forceinline__ uint32_t smem_u32(const void* p) {
    uint32_t a;
    asm("{ .reg .u64 t; cvta.to.shared.u64 t, %1; cvt.u32.u64 %0, t; }" : "=r"(a) : "l"(p));
    return a;
}
// 64-byte-row swizzle (rows are 64B here)
#define SWZ64(o) ((uint32_t)(o) ^ ((((uint32_t)(o)) >> 3) & 0x30))

__device__ __forceinline__ void cp16(uint32_t dst, const void* src) {
    asm volatile("cp.async.cg.shared.global [%0], [%1], 16;" :: "r"(dst), "l"(src) : "memory");
}
#define CP_COMMIT() asm volatile("cp.async.commit_group;" ::: "memory")

#define LDSM4(r0, r1, r2, r3, addr) \
    asm volatile("ldmatrix.sync.aligned.m8n8.x4.shared.b16 {%0,%1,%2,%3}, [%4];" \
                 : "=r"(r0), "=r"(r1), "=r"(r2), "=r"(r3) : "r"(addr))

#define MMA16816(c, a0, a1, a2, a3, b0, b1) \
    asm volatile("mma.sync.aligned.m16n8k16.row.col.f32.f16.f16.f32 " \
                 "{%0,%1,%2,%3}, {%4,%5,%6,%7}, {%8,%9}, {%0,%1,%2,%3};" \
                 : "+f"((c)[0]), "+f"((c)[1]), "+f"((c)[2]), "+f"((c)[3]) \
                 : "r"(a0), "r"(a1), "r"(a2), "r"(a3), "r"(b0), "r"(b1))

// ---------------------------------------------------------------------------
// Fused aux kernel: prep (wvec, c0) + W conversion + X conversion, one launch.
// ---------------------------------------------------------------------------
#define AUX_PREP_BLKS  128
#define AUX_WCONV_BLKS 2048
#define AUX_XCONV_BLKS 5120                 // 2560 per input (4 rows per block)
#define AUX_BLKS (AUX_PREP_BLKS + AUX_WCONV_BLKS + AUX_XCONV_BLKS)

__global__ __launch_bounds__(256)
void aux_kernel(const float* __restrict__ hist, const float* __restrict__ ques,
                const float* __restrict__ Wy_h, const float* __restrict__ Wg_h,
                const float* __restrict__ Wy_q, const float* __restrict__ Wg_q,
                const float* __restrict__ W1,   const float* __restrict__ b1,
                const float* __restrict__ W2,   const float* __restrict__ b2)
{
    __shared__ float tile[32][33];
    const int blk = blockIdx.x;
    const int t   = threadIdx.x;

    if (blk < AUX_PREP_BLKS) {
        const int warp = t >> 5;
        const int lane = t & 31;
        const int idx  = blk * 8 + warp;          // 0..1023
        float s = 0.f;
        #pragma unroll 4
        for (int m = lane; m < LL; m += 32)
            s += W1[(size_t)idx * LL + m] * W2[m];
        #pragma unroll
        for (int o = 16; o > 0; o >>= 1) s += __shfl_down_sync(0xFFFFFFFF, s, o);
        if (lane == 0) {
            if (idx < LL) g_wvec[0][idx] = s;
            else          g_wvec[1][idx - LL] = s;
        }
        if (blk == 0 && warp == 0) {
            float c = 0.f;
            #pragma unroll 4
            for (int m = lane; m < LL; m += 32) c += b1[m] * W2[m];
            #pragma unroll
            for (int o = 16; o > 0; o >>= 1) c += __shfl_down_sync(0xFFFFFFFF, c, o);
            if (lane == 0) g_c0 = c + b2[0];
        }
        return;
    }

    if (blk < AUX_PREP_BLKS + AUX_WCONV_BLKS) {
        const int wb = blk - AUX_PREP_BLKS;       // 0..2047
        const int kt = wb & 31;
        const int nt = (wb >> 5) & 31;
        const int inp = wb >> 10;
        const int tx = t & 31, ty = t >> 5;       // (32, 8)
        const float* W;
        int lbase;
        if (nt * 32 < 512) { W = inp ? Wy_q : Wy_h; lbase = nt * 32; }
        else               { W = inp ? Wg_q : Wg_h; lbase = nt * 32 - 512; }
        #pragma unroll
        for (int r = 0; r < 4; r++)
            tile[ty + r * 8][tx] = W[(size_t)(kt * 32 + ty + r * 8) * 512 + lbase + tx];
        __syncthreads();
        #pragma unroll
        for (int r = 0; r < 4; r++) {
            int nl = ty + r * 8;
            int n  = nt * 32 + nl;
            int k  = kt * 32 + tx;
            float f = tile[tx][nl] * 1024.0f;     // scale avoids fp16 denormal lo
            __half hi = __float2half_rn(f);
            __half lo = __float2half_rn(f - __half2float(hi));
            g_Wh[inp][n][k] = hi;
            g_Wl[inp][n][k] = lo;
        }
        return;
    }

    // ---- xconv: fp32 -> fp16 hi/lo planes, 4 rows per block ----
    {
        const int xb    = blk - AUX_PREP_BLKS - AUX_WCONV_BLKS;  // 0..5119
        const int input = xb / 2560;              // 2560 blocks per input
        const int row0  = (xb % 2560) * 4;
        const float* X  = input ? ques : hist;
        #pragma unroll
        for (int r = 0; r < 4; r++) {
            const int row = row0 + r;
            float4 f = *(const float4*)(X + (size_t)row * KK + t * 4);
            float fv[4] = {f.x, f.y, f.z, f.w};
            __half h[4], l[4];
            #pragma unroll
            for (int e = 0; e < 4; e++) {
                h[e] = __float2half_rn(fv[e]);
                l[e] = __float2half_rn(fv[e] - __half2float(h[e]));
            }
            *(uint2*)&g_Xh[input][row][t * 4] = *(uint2*)h;
            *(uint2*)&g_Xl[input][row][t * 4] = *(uint2*)l;
        }
    }
}

// ---------------------------------------------------------------------------
// HMMA GEMM + fused gated epilogue, plane-fused K loop (R13 config, measured
// best: total 326.4us). Stage (32KB) holds Xh, Xl, Wh, Wl for 32 k-halves
// (8KB each, 64B rows, SW64 swizzle); 12 LDSM per 48 MMAs.
// grid (80, 8, 2), block 256 (warps 4M x 2N). smem 3 x 32KB, 2 CTAs/SM.
// ---------------------------------------------------------------------------
__global__ __launch_bounds__(256, 2)
void gemm_hmma(const float* __restrict__ by_h, const float* __restrict__ bg_h,
               const float* __restrict__ by_q, const float* __restrict__ bg_q)
{
    extern __shared__ char smem[];
    const uint32_t sbase = smem_u32(smem);
    const int tid = threadIdx.x, wid = tid >> 5, lane = tid & 31;
    const int input = blockIdx.z, lc = blockIdx.y;
    const int m0 = blockIdx.x * 128;

    const __half* Xh = &g_Xh[input][0][0];
    const __half* Xl = &g_Xl[input][0][0];
    const __half* Wh = &g_Wh[input][0][0];
    const __half* Wl = &g_Wl[input][0][0];
    const float* by_ = input ? by_q : by_h;
    const float* bg_ = input ? bg_q : bg_h;

    const uint32_t T_XH = 0, T_XL = 8192, T_WH = 16384, T_WL = 24576;

    const int ldrow = tid >> 2;        // 0..63 (+64)
    const int ldseg = tid & 3;

    const int mw = wid >> 1;           // 0..3
    const int nw = wid & 1;            // 0..1
    const int q  = lane >> 3;
    const int r  = lane & 7;
    const int tq = lane & 3;
    const int grow = lane >> 2;        // 0..7

    const uint32_t aq16 = (uint32_t)((q >> 1) * 16);
    const uint32_t bq16 = (uint32_t)((q & 1) * 16);
    uint32_t a_base[2], a_xor[2];
    #pragma unroll
    for (int mt = 0; mt < 2; mt++) {
        int row = mw * 32 + mt * 16 + (q & 1) * 8 + r;
        a_base[mt] = (uint32_t)(row * 64);
        a_xor[mt]  = (uint32_t)((row & 6) << 3);
    }
    uint32_t bu_base[2], bu_xor[2], bv_base[2], bv_xor[2];
    #pragma unroll
    for (int bt = 0; bt < 2; bt++) {
        int rowu = nw * 32 + bt * 16 + (q >> 1) * 8 + r;
        bu_base[bt] = (uint32_t)(rowu * 64);
        bu_xor[bt]  = (uint32_t)((rowu & 6) << 3);
        int rowv = 64 + nw * 32 + bt * 16 + (q >> 1) * 8 + r;
        bv_base[bt] = (uint32_t)(rowv * 64);
        bv_xor[bt]  = (uint32_t)((rowv & 6) << 3);
    }

    float cu[2][4][4], cv[2][4][4];
    #pragma unroll
    for (int mt = 0; mt < 2; mt++)
        #pragma unroll
        for (int ut = 0; ut < 4; ut++)
            #pragma unroll
            for (int e = 0; e < 4; e++) { cu[mt][ut][e] = 0.f; cv[mt][ut][e] = 0.f; }

    auto load_stage = [&](int ko, int st) {
        const uint32_t sb = sbase + (uint32_t)st * 32768u;
        const int kb = ko * 64 + ldseg * 16;
        #pragma unroll
        for (int i = 0; i < 2; i++) {
            const int rr  = ldrow + i * 64;
            const uint32_t dsw = SWZ64(rr * 64 + ldseg * 16);
            const size_t xoff = (size_t)(m0 + rr) * 2048 + kb;
            cp16(sb + T_XH + dsw, (const char*)Xh + xoff);
            cp16(sb + T_XL + dsw, (const char*)Xl + xoff);
            const int ng = (rr < 64) ? (lc * 64 + rr) : (448 + lc * 64 + rr);
            const size_t woff = (size_t)ng * 2048 + kb;
            cp16(sb + T_WH + dsw, (const char*)Wh + woff);
            cp16(sb + T_WL + dsw, (const char*)Wl + woff);
        }
        CP_COMMIT();
    };

    load_stage(0, 0);
    load_stage(1, 1);

    int st_cur = 0;
    int st_nxt = 2;

    #pragma unroll 1
    for (int ko = 0; ko < NKO; ko++) {
        if (ko + 1 < NKO) {
            asm volatile("cp.async.wait_group 1;" ::: "memory");
        } else {
            asm volatile("cp.async.wait_group 0;" ::: "memory");
        }
        __syncthreads();

        if (ko + 2 < NKO)
            load_stage(ko + 2, st_nxt);

        const uint32_t sb = sbase + (uint32_t)st_cur * 32768u;

        #pragma unroll
        for (int s = 0; s < 2; s++) {
            const uint32_t csA = (uint32_t)(s * 32) + aq16;
            const uint32_t csB = (uint32_t)(s * 32) + bq16;

            // a = Xh fragments
            uint32_t a[2][4];
            #pragma unroll
            for (int mt = 0; mt < 2; mt++)
                LDSM4(a[mt][0], a[mt][1], a[mt][2], a[mt][3],
                      sb + T_XH + a_base[mt] + (csA ^ a_xor[mt]));

            // b = Wl fragments -> plane p2 = Xh*Wl
            {
                uint32_t bu[2][4], bv[2][4];
                #pragma unroll
                for (int bt = 0; bt < 2; bt++) {
                    LDSM4(bu[bt][0], bu[bt][1], bu[bt][2], bu[bt][3],
                          sb + T_WL + bu_base[bt] + (csB ^ bu_xor[bt]));
                    LDSM4(bv[bt][0], bv[bt][1], bv[bt][2], bv[bt][3],
                          sb + T_WL + bv_base[bt] + (csB ^ bv_xor[bt]));
                }
                #pragma unroll
                for (int mt = 0; mt < 2; mt++)
                    #pragma unroll
                    for (int bt = 0; bt < 2; bt++) {
                        MMA16816(cu[mt][2 * bt],     a[mt][0], a[mt][1], a[mt][2], a[mt][3], bu[bt][0], bu[bt][1]);
                        MMA16816(cu[mt][2 * bt + 1], a[mt][0], a[mt][1], a[mt][2], a[mt][3], bu[bt][2], bu[bt][3]);
                        MMA16816(cv[mt][2 * bt],     a[mt][0], a[mt][1], a[mt][2], a[mt][3], bv[bt][0], bv[bt][1]);
                        MMA16816(cv[mt][2 * bt + 1], a[mt][0], a[mt][1], a[mt][2], a[mt][3], bv[bt][2], bv[bt][3]);
                    }
            }

            // b = Wh fragments -> plane p0 = Xh*Wh, then a = Xl -> p1 = Xl*Wh
            {
                uint32_t bu[2][4], bv[2][4];
                #pragma unroll
                for (int bt = 0; bt < 2; bt++) {
                    LDSM4(bu[bt][0], bu[bt][1], bu[bt][2], bu[bt][3],
                          sb + T_WH + bu_base[bt] + (csB ^ bu_xor[bt]));
                    LDSM4(bv[bt][0], bv[bt][1], bv[bt][2], bv[bt][3],
                          sb + T_WH + bv_base[bt] + (csB ^ bv_xor[bt]));
                }
                #pragma unroll
                for (int mt = 0; mt < 2; mt++)
                    #pragma unroll
                    for (int bt = 0; bt < 2; bt++) {
                        MMA16816(cu[mt][2 * bt],     a[mt][0], a[mt][1], a[mt][2], a[mt][3], bu[bt][0], bu[bt][1]);
                        MMA16816(cu[mt][2 * bt + 1], a[mt][0], a[mt][1], a[mt][2], a[mt][3], bu[bt][2], bu[bt][3]);
                        MMA16816(cv[mt][2 * bt],     a[mt][0], a[mt][1], a[mt][2], a[mt][3], bv[bt][0], bv[bt][1]);
                        MMA16816(cv[mt][2 * bt + 1], a[mt][0], a[mt][1], a[mt][2], a[mt][3], bv[bt][2], bv[bt][3]);
                    }

                // overwrite a with Xl fragments
                #pragma unroll
                for (int mt = 0; mt < 2; mt++)
                    LDSM4(a[mt][0], a[mt][1], a[mt][2], a[mt][3],
                          sb + T_XL + a_base[mt] + (csA ^ a_xor[mt]));
                #pragma unroll
                for (int mt = 0; mt < 2; mt++)
                    #pragma unroll
                    for (int bt = 0; bt < 2; bt++) {
                        MMA16816(cu[mt][2 * bt],     a[mt][0], a[mt][1], a[mt][2], a[mt][3], bu[bt][0], bu[bt][1]);
                        MMA16816(cu[mt][2 * bt + 1], a[mt][0], a[mt][1], a[mt][2], a[mt][3], bu[bt][2], bu[bt][3]);
                        MMA16816(cv[mt][2 * bt],     a[mt][0], a[mt][1], a[mt][2], a[mt][3], bv[bt][0], bv[bt][1]);
                        MMA16816(cv[mt][2 * bt + 1], a[mt][0], a[mt][1], a[mt][2], a[mt][3], bv[bt][2], bv[bt][3]);
                    }
            }
        }

        st_cur = (st_cur == 2) ? 0 : st_cur + 1;
        st_nxt = (st_nxt == 2) ? 0 : st_nxt + 1;
    }

    // ---- fused epilogue ----
    __syncthreads();
    float* red = (float*)smem;            // [128][2]
    const float INV = 1.0f / 1024.0f;
    #pragma unroll
    for (int mt = 0; mt < 2; mt++) {
        float p0 = 0.f, p1 = 0.f;
        #pragma unroll
        for (int ut = 0; ut < 4; ut++) {
            #pragma unroll
            for (int e = 0; e < 2; e++) {
                int l = lc * 64 + nw * 32 + ut * 8 + tq * 2 + e;
                float byv = __ldg(by_ + l);
                float bgv = __ldg(bg_ + l);
                float wv  = g_wvec[input][l];
                float u0 = cu[mt][ut][e] * INV + byv;
                float v0 = cv[mt][ut][e] * INV + bgv;
                p0 += tanhf(u0) * (1.f / (1.f + expf(-v0))) * wv;
                float u1 = cu[mt][ut][2 + e] * INV + byv;
                float v1 = cv[mt][ut][2 + e] * INV + bgv;
                p1 += tanhf(u1) * (1.f / (1.f + expf(-v1))) * wv;
            }
        }
        p0 += __shfl_down_sync(0xFFFFFFFF, p0, 2);
        p0 += __shfl_down_sync(0xFFFFFFFF, p0, 1);
        p1 += __shfl_down_sync(0xFFFFFFFF, p1, 2);
        p1 += __shfl_down_sync(0xFFFFFFFF, p1, 1);
        if (tq == 0) {
            int row = mw * 32 + mt * 16 + grow;
            red[row * 2 + nw]       = p0;
            red[(row + 8) * 2 + nw] = p1;
        }
    }
    __syncthreads();
    if (tid < 128)
        g_tpart[input][m0 + tid][lc] = red[tid * 2] + red[tid * 2 + 1];
}

// ---------------------------------------------------------------------------
// Final: logits + Gumbel, argmax over prefix, one-hot write.
// Block-cooperative: history row-sums for the block's batch range are
// computed ONCE into smem (same c=0..7 order -> bitwise-identical scores),
// removing the ~10x redundant global reads of g_tpart[0].
// ---------------------------------------------------------------------------
__global__ __launch_bounds__(256)
void final_kernel(const float* __restrict__ noise,
                  const float* __restrict__ Wa, const float* __restrict__ ba,
                  float* __restrict__ out)
{
    __shared__ float hsum[272];              // history sums for block's rows
    const int t0  = blockIdx.x * 256;
    const int tid = threadIdx.x;
    const int t   = t0 + tid;

    const int b_first = t0 / RR;
    const int b_last  = (t0 + 255) / RR;
    const int nrows   = (b_last - b_first + 1) * RR;   // <= 270
    const int r0      = b_first * RR;

    for (int rr = tid; rr < nrows; rr += 256) {
        float s = 0.f;
        #pragma unroll
        for (int c = 0; c < NLCH; c++) s += g_tpart[0][r0 + rr][c];
        hsum[rr] = s;
    }
    __syncthreads();

    if (t >= BRD) return;
    const int b = t / RR;
    const int i = t % RR;

    float Wa0 = Wa[0], Wa1 = Wa[1], ba0 = ba[0], c0 = g_c0;
    float tq = 0.f;
    #pragma unroll
    for (int c = 0; c < NLCH; c++) tq += g_tpart[1][t][c];

    const float* hs = &hsum[(b - b_first) * RR];
    float best = -3.4e38f;
    int bj = 0;
    for (int j = 0; j <= i; j++) {
        float score = tq + hs[j] + c0;
        float logit = score * Wa0 + (float)(i - j + 1) * Wa1 + ba0;
        float ns = noise[(size_t)b * RR * RR + i * RR + j];
        float gm = -logf(1e-10f - logf(ns + 1e-10f));
        float z  = logit + gm;
        if (z > best) { best = z; bj = j; }   // strict > keeps first max
    }
    float* o = out + (size_t)b * RR * RR + (size_t)i * RR;
    #pragma unroll
    for (int j = 0; j < RR; j++) o[j] = (j == bj) ? 1.f : 0.f;
}

// ---------------------------------------------------------------------------
extern "C" void kernel_launch(void* const* d_in, const int* in_sizes, int n_in,
                              void* d_out, int out_size)
{
    const float* hist  = (const float*)d_in[0];
    const float* ques  = (const float*)d_in[1];
    const float* noise = (const float*)d_in[2];
    const float* Wy_h  = (const float*)d_in[3];
    const float* by_h  = (const float*)d_in[4];
    const float* Wg_h  = (const float*)d_in[5];
    const float* bg_h  = (const float*)d_in[6];
    const float* Wy_q  = (const float*)d_in[7];
    const float* by_q  = (const float*)d_in[8];
    const float* Wg_q  = (const float*)d_in[9];
    const float* bg_q  = (const float*)d_in[10];
    const float* W1    = (const float*)d_in[11];
    const float* b1    = (const float*)d_in[12];
    const float* W2    = (const float*)d_in[13];
    const float* b2    = (const float*)d_in[14];
    const float* Wa    = (const float*)d_in[15];
    const float* ba    = (const float*)d_in[16];
    float* out = (float*)d_out;

    cudaFuncSetAttribute(gemm_hmma, cudaFuncAttributeMaxDynamicSharedMemorySize, 98304);

    aux_kernel<<<AUX_BLKS, 256>>>(hist, ques, Wy_h, Wg_h, Wy_q, Wg_q,
                                  W1, b1, W2, b2);

    gemm_hmma<<<dim3(80, NLCH, 2), 256, 98304>>>(by_h, bg_h, by_q, bg_q);

    final_kernel<<<(BRD + 255) / 256, 256>>>(noise, Wa, ba, out);
}